// round 13
// baseline (speedup 1.0000x reference)
#include <cuda_runtime.h>
#include <cuda_fp16.h>
#include <mma.h>
#include <stdint.h>

using namespace nvcuda;

#define B_   32
#define S_   512
#define H_   512
#define E_   512
#define G4H  2048
#define BS_  (B_*S_)          // 16384
#define BH_  (B_*H_)          // 16384

// ---------------- scratch (__device__ globals; no allocation allowed) ----------------
__device__ __half g_X0h[BS_*E_];
__device__ __half g_X0l[BS_*E_];
__device__ __half g_y0h[BS_*2*H_];
__device__ __half g_y0l[BS_*2*H_];
__device__ __half g_y1h[BS_*2*H_];
__device__ __half g_y1l[BS_*2*H_];
__device__ float  g_xp0[(size_t)BS_*G4H];
__device__ float  g_xp1[(size_t)BS_*G4H];
__device__ __half g_Wih_h[2*2*(size_t)G4H*1024];   // [layer][dir], K up to 1024
__device__ __half g_Wih_l[2*2*(size_t)G4H*1024];
__device__ __half g_Whh_h[2*2*(size_t)G4H*H_];
__device__ __half g_Whh_l[2*2*(size_t)G4H*H_];
__device__ float  g_bsum[2*2*G4H];
__device__ __half g_hbh[2*2*BH_];
__device__ __half g_hbl[2*2*BH_];
__device__ float  g_pool[32*8*1024];
__device__ float  g_cntp[32*8];
// per-direction barrier state (R3-proven protocol, one instance per direction,
// instances 128B apart -> distinct L2 lines)
__device__ unsigned g_bar_cnt[2*32];
__device__ unsigned g_bar_gen[2*32];

// ---------------- prep kernels ----------------
__device__ __forceinline__ void split_one(const float* __restrict__ src,
                                          __half* __restrict__ dh,
                                          __half* __restrict__ dl, int i) {
    float4 v = ((const float4*)src)[i];
    __half h0 = __float2half(v.x), h1 = __float2half(v.y);
    __half h2 = __float2half(v.z), h3 = __float2half(v.w);
    __half2* dhp = (__half2*)(dh + (size_t)i * 4);
    __half2* dlp = (__half2*)(dl + (size_t)i * 4);
    dhp[0] = __halves2half2(h0, h1);
    dhp[1] = __halves2half2(h2, h3);
    dlp[0] = __floats2half2_rn(v.x - __half2float(h0), v.y - __half2float(h1));
    dlp[1] = __floats2half2_rn(v.z - __half2float(h2), v.w - __half2float(h3));
}

__global__ void k_split2(const float* __restrict__ s0, const float* __restrict__ s1,
                         __half* __restrict__ dh, __half* __restrict__ dl,
                         size_t stride, int n4) {
    int i = blockIdx.x * blockDim.x + threadIdx.x;
    const float* s = blockIdx.y ? s1 : s0;
    if (i < n4) split_one(s, dh + blockIdx.y * stride, dl + blockIdx.y * stride, i);
}

__global__ void k_split4(const float* __restrict__ s0, const float* __restrict__ s1,
                         const float* __restrict__ s2, const float* __restrict__ s3,
                         __half* __restrict__ dh, __half* __restrict__ dl,
                         size_t stride, int n4) {
    int i = blockIdx.x * blockDim.x + threadIdx.x;
    const float* sel[4] = {s0, s1, s2, s3};
    const float* s = sel[blockIdx.y];
    if (i < n4) split_one(s, dh + blockIdx.y * stride, dl + blockIdx.y * stride, i);
}

// fused bias-sum (blocks 0..31) + embedding split (blocks 32..)
__global__ void k_misc(const int* __restrict__ x, const float* __restrict__ emb,
                       __half* __restrict__ oh, __half* __restrict__ ol,
                       const float* __restrict__ a0, const float* __restrict__ b0,
                       const float* __restrict__ a1, const float* __restrict__ b1,
                       const float* __restrict__ a2, const float* __restrict__ b2,
                       const float* __restrict__ a3, const float* __restrict__ b3,
                       float* __restrict__ bs) {
    if (blockIdx.x < 32) {
        int i = blockIdx.x * 256 + threadIdx.x;      // 0..8191
        int job = i >> 11, e = i & 2047;
        const float* sa[4] = {a0, a1, a2, a3};
        const float* sb[4] = {b0, b1, b2, b3};
        bs[job * 2048 + e] = sa[job][e] + sb[job][e];
        return;
    }
    int chunk = (blockIdx.x - 32) * 256 + threadIdx.x;
    if (chunk < BS_ * (E_ / 4)) {
        int i = chunk >> 7;
        int j = chunk & 127;
        int tok = x[i];
        float4 v = ((const float4*)emb)[(size_t)tok * (E_ / 4) + j];
        __half h0 = __float2half(v.x), h1 = __float2half(v.y);
        __half h2 = __float2half(v.z), h3 = __float2half(v.w);
        __half2* dh = (__half2*)(oh + (size_t)i * E_ + j * 4);
        __half2* dl = (__half2*)(ol + (size_t)i * E_ + j * 4);
        dh[0] = __halves2half2(h0, h1);
        dh[1] = __halves2half2(h2, h3);
        dl[0] = __floats2half2_rn(v.x - __half2float(h0), v.y - __half2float(h1));
        dl[1] = __floats2half2_rn(v.z - __half2float(h2), v.w - __half2float(h3));
    }
}

// ---------------- 3-term split GEMM, 4-tile stages: C[16384,2048] ----------------
// C = Ah*Wh^T + Al*Wh^T + Ah*Wl^T. Stage loads {Ah,Al,Wh,Wl} once; 3 products per stage.
#define GBM 128
#define GBN 128
#define GBK 32
#define LDA 40
#define TSZ (GBM*LDA)        // 5120 halves per tile
#define STG4 (4*TSZ)         // 20480 halves
#define GSM3 (2*STG4*2)      // 81920 B

__device__ __forceinline__ void cpasync16(void* s, const void* g) {
    uint32_t sa = (uint32_t)__cvta_generic_to_shared(s);
    asm volatile("cp.async.cg.shared.global [%0], [%1], 16;\n" :: "r"(sa), "l"(g));
}

__global__ __launch_bounds__(256) void k_gemm(const __half* __restrict__ Ah,
                                              const __half* __restrict__ Al,
                                              const __half* __restrict__ Wh,
                                              const __half* __restrict__ Wl,
                                              float* __restrict__ C, int K) {
    extern __shared__ __half gsm[];
    int tid = threadIdx.x;
    int bm = blockIdx.y, bn = blockIdx.x;
    int wid = tid >> 5;
    int wm = wid & 3;        // 4 m-rows of 32
    int wn = wid >> 2;       // 2 n-cols of 64

    wmma::fragment<wmma::accumulator, 16, 16, 16, float> acc[2][4];
    #pragma unroll
    for (int i = 0; i < 2; i++)
        #pragma unroll
        for (int j = 0; j < 4; j++) wmma::fill_fragment(acc[i][j], 0.f);

    int NT = K / GBK;

    auto issue = [&](int kt) {
        const __half* s0 = Ah + (size_t)(bm * GBM) * K + kt * GBK;
        const __half* s1 = Al + (size_t)(bm * GBM) * K + kt * GBK;
        const __half* s2 = Wh + (size_t)(bn * GBN) * K + kt * GBK;
        const __half* s3 = Wl + (size_t)(bn * GBN) * K + kt * GBK;
        __half* dst = gsm + (kt & 1) * STG4;
        #pragma unroll
        for (int j = 0; j < 8; j++) {
            int c = tid + j * 256;           // 0..2047
            int tsel = c >> 9;               // 0:Ah 1:Al 2:Wh 3:Wl
            int cw = c & 511;
            int row = cw >> 2, cc = (cw & 3) * 8;
            const __half* s = (tsel == 0) ? s0 : (tsel == 1) ? s1 : (tsel == 2) ? s2 : s3;
            cpasync16(dst + tsel * TSZ + row * LDA + cc, s + (size_t)row * K + cc);
        }
        asm volatile("cp.async.commit_group;\n");
    };

    issue(0);

    for (int kt = 0; kt < NT; kt++) {
        if (kt + 1 < NT) {
            issue(kt + 1);
            asm volatile("cp.async.wait_group 1;\n");
        } else {
            asm volatile("cp.async.wait_group 0;\n");
        }
        __syncthreads();
        const __half* Ahs = gsm + (kt & 1) * STG4;
        const __half* Als = Ahs + TSZ;
        const __half* Whs = Ahs + 2 * TSZ;
        const __half* Wls = Ahs + 3 * TSZ;
        #pragma unroll
        for (int kk = 0; kk < 2; kk++) {
            wmma::fragment<wmma::matrix_a, 16, 16, 16, __half, wmma::row_major> afh[2], afl[2];
            #pragma unroll
            for (int i = 0; i < 2; i++) {
                wmma::load_matrix_sync(afh[i], Ahs + (wm * 32 + i * 16) * LDA + kk * 16, LDA);
                wmma::load_matrix_sync(afl[i], Als + (wm * 32 + i * 16) * LDA + kk * 16, LDA);
            }
            #pragma unroll
            for (int j = 0; j < 4; j++) {
                wmma::fragment<wmma::matrix_b, 16, 16, 16, __half, wmma::col_major> bfh, bfl;
                wmma::load_matrix_sync(bfh, Whs + (wn * 64 + j * 16) * LDA + kk * 16, LDA);
                wmma::load_matrix_sync(bfl, Wls + (wn * 64 + j * 16) * LDA + kk * 16, LDA);
                #pragma unroll
                for (int i = 0; i < 2; i++) {
                    wmma::mma_sync(acc[i][j], afh[i], bfh, acc[i][j]);
                    wmma::mma_sync(acc[i][j], afl[i], bfh, acc[i][j]);
                    wmma::mma_sync(acc[i][j], afh[i], bfl, acc[i][j]);
                }
            }
        }
        __syncthreads();
    }

    #pragma unroll
    for (int i = 0; i < 2; i++)
        #pragma unroll
        for (int j = 0; j < 4; j++) {
            int row = bm * GBM + wm * 32 + i * 16;
            int col = bn * GBN + wn * 64 + j * 16;
            wmma::store_matrix_sync(C + (size_t)row * G4H + col, acc[i][j], G4H,
                                    wmma::mem_row_major);
        }
}

// ---------------- persistent bidirectional LSTM recurrence ----------------
#define RNB 128
#define DNB 64               // CTAs per direction
#define LDH 520
#define LDGS 36
#define RECSM (3*32*LDH*2 + 32*LDGS*4)

// R3-proven single-counter barrier, one independent instance per direction.
// Reset is ATOMIC (atomicExch) by the releasing CTA before the gen increment.
__device__ __forceinline__ void gridbar(int dir) {
    __syncthreads();
    if (threadIdx.x == 0) {
        volatile unsigned* vg = &g_bar_gen[dir * 32];
        unsigned gen = *vg;
        __threadfence();
        unsigned t = atomicAdd(&g_bar_cnt[dir * 32], 1u);
        if (t == DNB - 1) {
            atomicExch(&g_bar_cnt[dir * 32], 0u);
            __threadfence();
            atomicAdd((unsigned*)&g_bar_gen[dir * 32], 1u);
        } else {
            while (*vg == gen) { }
        }
        __threadfence();
    }
    __syncthreads();
}

__device__ __forceinline__ float sigmoidf_(float x) { return 1.f / (1.f + __expf(-x)); }
__device__ __forceinline__ float tanhf_(float x) {
    x = fminf(fmaxf(x, -15.f), 15.f);
    float e = __expf(2.f * x);
    return (e - 1.f) / (e + 1.f);
}

__global__ __launch_bounds__(128) void k_rec(const float* __restrict__ xpf,
                                             const float* __restrict__ xpb,
                                             const __half* __restrict__ Whf_h,
                                             const __half* __restrict__ Whf_l,
                                             const __half* __restrict__ Whb_h,
                                             const __half* __restrict__ Whb_l,
                                             const float* __restrict__ bsf,
                                             const float* __restrict__ bsb,
                                             __half* __restrict__ yh,
                                             __half* __restrict__ yl) {
    extern __shared__ char smraw[];
    __half* Wlo = (__half*)smraw;
    __half* Hhi = (__half*)(smraw + 32 * LDH * 2);
    __half* Hlo = (__half*)(smraw + 2 * 32 * LDH * 2);
    float*  Gs  = (float*)(smraw + 3 * 32 * LDH * 2);

    int tid = threadIdx.x;
    int blk = blockIdx.x;
    int dir = blk >> 6;
    int grp = blk & 63;
    int ub  = grp * 8;
    const __half* Wh_h = dir ? Whb_h : Whf_h;
    const __half* Wh_l = dir ? Whb_l : Whf_l;
    const float*  xp   = dir ? xpb : xpf;
    const float*  bs   = dir ? bsb : bsf;

    for (int chunk = tid; chunk < 32 * 64; chunk += 128) {
        int c = chunk >> 6, w8 = (chunk & 63) * 8;
        int q = c >> 3, u = c & 7;
        uint4 v = *(const uint4*)(Wh_h + (size_t)(q * H_ + ub + u) * H_ + w8);
        *(uint4*)(Hhi + c * LDH + w8) = v;
    }

    float bias[2][4];
    float cst[2] = {0.f, 0.f};
    #pragma unroll
    for (int j = 0; j < 2; j++) {
        int it = tid + 128 * j;
        int b = it >> 3, u = it & 7;
        #pragma unroll
        for (int q = 0; q < 4; q++) bias[j][q] = bs[q * H_ + ub + u];
        __stcg((unsigned short*)&g_hbh[(0 * 2 + dir) * BH_ + b * H_ + ub + u], (unsigned short)0);
        __stcg((unsigned short*)&g_hbl[(0 * 2 + dir) * BH_ + b * H_ + ub + u], (unsigned short)0);
    }
    __syncthreads();

    int wid = tid >> 5;
    int mi = wid & 1;
    int ni = wid >> 1;
    wmma::fragment<wmma::matrix_b, 16, 16, 16, __half, wmma::col_major> bfr[32];
    #pragma unroll
    for (int kk = 0; kk < 32; kk++)
        wmma::load_matrix_sync(bfr[kk], Hhi + (ni * 16) * LDH + kk * 16, LDH);
    __syncthreads();

    for (int chunk = tid; chunk < 32 * 64; chunk += 128) {
        int c = chunk >> 6, w8 = (chunk & 63) * 8;
        int q = c >> 3, u = c & 7;
        uint4 v = *(const uint4*)(Wh_l + (size_t)(q * H_ + ub + u) * H_ + w8);
        *(uint4*)(Wlo + c * LDH + w8) = v;
    }

    __threadfence();          // release h zero-init (all threads)
    gridbar(dir);

    for (int s = 0; s < S_; s++) {
        int p = s & 1;

        // prefetch this step's xp rows early (independent of h)
        int t = dir ? (S_ - 1 - s) : s;
        float px[2][4];
        #pragma unroll
        for (int j = 0; j < 2; j++) {
            int it = tid + 128 * j;
            int b = it >> 3, u = it & 7;
            const float* xr = xp + (size_t)(b * S_ + t) * G4H + ub + u;
            px[j][0] = __ldg(xr);
            px[j][1] = __ldg(xr + 512);
            px[j][2] = __ldg(xr + 1024);
            px[j][3] = __ldg(xr + 1536);
        }

        const __half* hsh = &g_hbh[(p * 2 + dir) * BH_];
        const __half* hsl = &g_hbl[(p * 2 + dir) * BH_];
        for (int chunk = tid; chunk < 32 * 64; chunk += 128) {
            int b = chunk >> 6, w8 = (chunk & 63) * 8;
            uint4 vh = __ldcg((const uint4*)(hsh + b * H_ + w8));
            uint4 vl = __ldcg((const uint4*)(hsl + b * H_ + w8));
            *(uint4*)(Hhi + b * LDH + w8) = vh;
            *(uint4*)(Hlo + b * LDH + w8) = vl;
        }
        __syncthreads();

        wmma::fragment<wmma::accumulator, 16, 16, 16, float> acc;
        wmma::fill_fragment(acc, 0.f);
        #pragma unroll
        for (int kk = 0; kk < 32; kk++) {
            wmma::fragment<wmma::matrix_a, 16, 16, 16, __half, wmma::row_major> ah, al;
            wmma::fragment<wmma::matrix_b, 16, 16, 16, __half, wmma::col_major> bl;
            wmma::load_matrix_sync(ah, Hhi + (mi * 16) * LDH + kk * 16, LDH);
            wmma::load_matrix_sync(al, Hlo + (mi * 16) * LDH + kk * 16, LDH);
            wmma::load_matrix_sync(bl, Wlo + (ni * 16) * LDH + kk * 16, LDH);
            wmma::mma_sync(acc, ah, bfr[kk], acc);
            wmma::mma_sync(acc, al, bfr[kk], acc);
            wmma::mma_sync(acc, ah, bl, acc);
        }
        wmma::store_matrix_sync(Gs + (mi * 16) * LDGS + ni * 16, acc, LDGS, wmma::mem_row_major);
        __syncthreads();

        #pragma unroll
        for (int j = 0; j < 2; j++) {
            int it = tid + 128 * j;
            int b = it >> 3, u = it & 7;
            float gi = Gs[b * LDGS + u]       + px[j][0] + bias[j][0];
            float gf = Gs[b * LDGS + 8 + u]   + px[j][1] + bias[j][1];
            float gg = Gs[b * LDGS + 16 + u]  + px[j][2] + bias[j][2];
            float go = Gs[b * LDGS + 24 + u]  + px[j][3] + bias[j][3];
            float cc = sigmoidf_(gf) * cst[j] + sigmoidf_(gi) * tanhf_(gg);
            cst[j] = cc;
            float h = sigmoidf_(go) * tanhf_(cc);
            __half hh = __float2half(h);
            __half hl = __float2half(h - __half2float(hh));
            int ho = ((p ^ 1) * 2 + dir) * BH_ + b * H_ + ub + u;
            __stcg((unsigned short*)&g_hbh[ho], __half_as_ushort(hh));
            __stcg((unsigned short*)&g_hbl[ho], __half_as_ushort(hl));
            size_t yo = (size_t)(b * S_ + t) * (2 * H_) + dir * H_ + ub + u;
            yh[yo] = hh;
            yl[yo] = hl;
        }
        __threadfence();      // release this step's h stores (all threads)
        gridbar(dir);
    }
}

// ---------------- pooling partials + FC ----------------
__global__ __launch_bounds__(256) void k_ppart(const __half* __restrict__ yh,
                                               const __half* __restrict__ yl,
                                               const int* __restrict__ mask,
                                               float* __restrict__ pool,
                                               float* __restrict__ cntp) {
    int b = blockIdx.x, sc = blockIdx.y, tid = threadIdx.x;
    float acc[4] = {0.f, 0.f, 0.f, 0.f};
    float mcount = 0.f;
    for (int ss = 0; ss < 64; ss++) {
        int s = sc * 64 + ss;
        float m = (float)mask[b * S_ + s];
        mcount += m;
        const __half* yrh = yh + (size_t)(b * S_ + s) * 1024;
        const __half* yrl = yl + (size_t)(b * S_ + s) * 1024;
        #pragma unroll
        for (int j = 0; j < 4; j++) {
            int k = tid + j * 256;
            acc[j] += m * (__half2float(yrh[k]) + __half2float(yrl[k]));
        }
    }
    float* prow = pool + (size_t)(b * 8 + sc) * 1024;
    #pragma unroll
    for (int j = 0; j < 4; j++) prow[tid + j * 256] = acc[j];
    if (tid == 0) cntp[b * 8 + sc] = mcount;
}

__global__ __launch_bounds__(256) void k_fc(const float* __restrict__ pool,
                                            const float* __restrict__ cntp,
                                            const float* __restrict__ fcW,
                                            const float* __restrict__ fcb,
                                            float* __restrict__ out) {
    int b = blockIdx.x, tid = threadIdx.x;
    __shared__ float red[256];
    float cnt = 0.f;
    #pragma unroll
    for (int p = 0; p < 8; p++) cnt += cntp[b * 8 + p];
    float inv = 1.f / fmaxf(cnt, 1e-9f);
    float pooled[4];
    #pragma unroll
    for (int j = 0; j < 4; j++) {
        int col = tid + j * 256;
        float sum = 0.f;
        #pragma unroll
        for (int p = 0; p < 8; p++) sum += pool[(size_t)(b * 8 + p) * 1024 + col];
        pooled[j] = sum * inv;
    }
    for (int c = 0; c < 2; c++) {
        float pv = 0.f;
        #pragma unroll
        for (int j = 0; j < 4; j++) {
            int k = tid + j * 256;
            pv += pooled[j] * fcW[c * 1024 + k];
        }
        red[tid] = pv;
        __syncthreads();
        for (int st = 128; st > 0; st >>= 1) {
            if (tid < st) red[tid] += red[tid + st];
            __syncthreads();
        }
        if (tid == 0) out[b * 2 + c] = red[0] + fcb[c];
        __syncthreads();
    }
}

// ---------------- host orchestration ----------------
extern "C" void kernel_launch(void* const* d_in, const int* in_sizes, int n_in,
                              void* d_out, int out_size) {
    const int*   x   = (const int*)d_in[0];
    const int*   am  = (const int*)d_in[1];
    const float* emb = (const float*)d_in[2];
    const float* fcW = (const float*)d_in[3];
    const float* fcb = (const float*)d_in[4];
    const float* Wih[2][2] = {{(const float*)d_in[5],  (const float*)d_in[9]},
                              {(const float*)d_in[13], (const float*)d_in[17]}};
    const float* Whh[2][2] = {{(const float*)d_in[6],  (const float*)d_in[10]},
                              {(const float*)d_in[14], (const float*)d_in[18]}};
    const float* bih[2][2] = {{(const float*)d_in[7],  (const float*)d_in[11]},
                              {(const float*)d_in[15], (const float*)d_in[19]}};
    const float* bhh[2][2] = {{(const float*)d_in[8],  (const float*)d_in[12]},
                              {(const float*)d_in[16], (const float*)d_in[20]}};

    void *pX0h, *pX0l, *py0h, *py0l, *py1h, *py1l, *pxp0, *pxp1;
    void *pWihH, *pWihL, *pWhhH, *pWhhL, *pbs, *ppool, *pcnt;
    cudaGetSymbolAddress(&pX0h, g_X0h);
    cudaGetSymbolAddress(&pX0l, g_X0l);
    cudaGetSymbolAddress(&py0h, g_y0h);
    cudaGetSymbolAddress(&py0l, g_y0l);
    cudaGetSymbolAddress(&py1h, g_y1h);
    cudaGetSymbolAddress(&py1l, g_y1l);
    cudaGetSymbolAddress(&pxp0, g_xp0);
    cudaGetSymbolAddress(&pxp1, g_xp1);
    cudaGetSymbolAddress(&pWihH, g_Wih_h);
    cudaGetSymbolAddress(&pWihL, g_Wih_l);
    cudaGetSymbolAddress(&pWhhH, g_Whh_h);
    cudaGetSymbolAddress(&pWhhL, g_Whh_l);
    cudaGetSymbolAddress(&pbs,  g_bsum);
    cudaGetSymbolAddress(&ppool, g_pool);
    cudaGetSymbolAddress(&pcnt,  g_cntp);

    cudaFuncSetAttribute(k_rec,  cudaFuncAttributeMaxDynamicSharedMemorySize, RECSM);
    cudaFuncSetAttribute(k_gemm, cudaFuncAttributeMaxDynamicSharedMemorySize, GSM3);

    const size_t WIH_STRIDE = (size_t)G4H * 1024;
    const size_t WHH_STRIDE = (size_t)G4H * H_;

    // prep (4 launches)
    {
        int n4 = G4H * E_ / 4;
        k_split2<<<dim3((n4 + 255) / 256, 2), 256>>>(Wih[0][0], Wih[0][1],
                                                     (__half*)pWihH, (__half*)pWihL,
                                                     WIH_STRIDE, n4);
        int n4b = G4H * 1024 / 4;
        k_split2<<<dim3((n4b + 255) / 256, 2), 256>>>(Wih[1][0], Wih[1][1],
                                                      (__half*)pWihH + 2 * WIH_STRIDE,
                                                      (__half*)pWihL + 2 * WIH_STRIDE,
                                                      WIH_STRIDE, n4b);
        int n4h = G4H * H_ / 4;
        k_split4<<<dim3((n4h + 255) / 256, 4), 256>>>(Whh[0][0], Whh[0][1], Whh[1][0], Whh[1][1],
                                                      (__half*)pWhhH, (__half*)pWhhL,
                                                      WHH_STRIDE, n4h);
        k_misc<<<32 + (BS_ * (E_ / 4) + 255) / 256, 256>>>(
            x, emb, (__half*)pX0h, (__half*)pX0l,
            bih[0][0], bhh[0][0], bih[0][1], bhh[0][1],
            bih[1][0], bhh[1][0], bih[1][1], bhh[1][1], (float*)pbs);
    }

    dim3 gg(G4H / GBN, BS_ / GBM);   // (16, 128)

    // ----- layer 0 -----
    k_gemm<<<gg, 256, GSM3>>>((const __half*)pX0h, (const __half*)pX0l,
                              (const __half*)pWihH + 0 * WIH_STRIDE,
                              (const __half*)pWihL + 0 * WIH_STRIDE, (float*)pxp0, E_);
    k_gemm<<<gg, 256, GSM3>>>((const __half*)pX0h, (const __half*)pX0l,
                              (const __half*)pWihH + 1 * WIH_STRIDE,
                              (const __half*)pWihL + 1 * WIH_STRIDE, (float*)pxp1, E_);
    k_rec<<<RNB, 128, RECSM>>>((const float*)pxp0, (const float*)pxp1,
                               (const __half*)pWhhH + 0 * WHH_STRIDE,
                               (const __half*)pWhhL + 0 * WHH_STRIDE,
                               (const __half*)pWhhH + 1 * WHH_STRIDE,
                               (const __half*)pWhhL + 1 * WHH_STRIDE,
                               (const float*)pbs + 0 * G4H, (const float*)pbs + 1 * G4H,
                               (__half*)py0h, (__half*)py0l);

    // ----- layer 1 -----
    k_gemm<<<gg, 256, GSM3>>>((const __half*)py0h, (const __half*)py0l,
                              (const __half*)pWihH + 2 * WIH_STRIDE,
                              (const __half*)pWihL + 2 * WIH_STRIDE, (float*)pxp0, 2 * H_);
    k_gemm<<<gg, 256, GSM3>>>((const __half*)py0h, (const __half*)py0l,
                              (const __half*)pWihH + 3 * WIH_STRIDE,
                              (const __half*)pWihL + 3 * WIH_STRIDE, (float*)pxp1, 2 * H_);
    k_rec<<<RNB, 128, RECSM>>>((const float*)pxp0, (const float*)pxp1,
                               (const __half*)pWhhH + 2 * WHH_STRIDE,
                               (const __half*)pWhhL + 2 * WHH_STRIDE,
                               (const __half*)pWhhH + 3 * WHH_STRIDE,
                               (const __half*)pWhhL + 3 * WHH_STRIDE,
                               (const float*)pbs + 2 * G4H, (const float*)pbs + 3 * G4H,
                               (__half*)py1h, (__half*)py1l);

    // ----- pool + fc -----
    k_ppart<<<dim3(32, 8), 256>>>((const __half*)py1h, (const __half*)py1l, am,
                                  (float*)ppool, (float*)pcnt);
    k_fc<<<32, 256>>>((const float*)ppool, (const float*)pcnt, fcW, fcb, (float*)d_out);
}

// round 14
// speedup vs baseline: 1.0323x; 1.0323x over previous
#include <cuda_runtime.h>
#include <cuda_fp16.h>
#include <mma.h>
#include <stdint.h>

using namespace nvcuda;

#define B_   32
#define S_   512
#define H_   512
#define E_   512
#define G4H  2048
#define BS_  (B_*S_)          // 16384
#define BH_  (B_*H_)          // 16384

// ---------------- scratch (__device__ globals; no allocation allowed) ----------------
__device__ __half g_X0h[BS_*E_];
__device__ __half g_X0l[BS_*E_];
__device__ __half g_y0h[BS_*2*H_];
__device__ __half g_y0l[BS_*2*H_];
__device__ __half g_y1h[BS_*2*H_];
__device__ __half g_y1l[BS_*2*H_];
__device__ float  g_xp0[(size_t)BS_*G4H];
__device__ float  g_xp1[(size_t)BS_*G4H];
__device__ __half g_Wih_h[2*2*(size_t)G4H*1024];   // [layer][dir], K up to 1024
__device__ __half g_Wih_l[2*2*(size_t)G4H*1024];
__device__ __half g_Whh_h[2*2*(size_t)G4H*H_];
__device__ __half g_Whh_l[2*2*(size_t)G4H*H_];
__device__ float  g_bsum[2*2*G4H];
__device__ __half g_hbh[2*2*BH_];
__device__ __half g_hbl[2*2*BH_];
__device__ float  g_pool[32*8*1024];
__device__ float  g_cntp[32*8];
// per-direction barrier state (R3-proven protocol, one instance per direction,
// instances 128B apart -> distinct L2 lines)
__device__ unsigned g_bar_cnt[2*32];
__device__ unsigned g_bar_gen[2*32];

// ---------------- prep kernels ----------------
__device__ __forceinline__ void split_one(const float* __restrict__ src,
                                          __half* __restrict__ dh,
                                          __half* __restrict__ dl, int i) {
    float4 v = ((const float4*)src)[i];
    __half h0 = __float2half(v.x), h1 = __float2half(v.y);
    __half h2 = __float2half(v.z), h3 = __float2half(v.w);
    __half2* dhp = (__half2*)(dh + (size_t)i * 4);
    __half2* dlp = (__half2*)(dl + (size_t)i * 4);
    dhp[0] = __halves2half2(h0, h1);
    dhp[1] = __halves2half2(h2, h3);
    dlp[0] = __floats2half2_rn(v.x - __half2float(h0), v.y - __half2float(h1));
    dlp[1] = __floats2half2_rn(v.z - __half2float(h2), v.w - __half2float(h3));
}

__global__ void k_split2(const float* __restrict__ s0, const float* __restrict__ s1,
                         __half* __restrict__ dh, __half* __restrict__ dl,
                         size_t stride, int n4) {
    int i = blockIdx.x * blockDim.x + threadIdx.x;
    const float* s = blockIdx.y ? s1 : s0;
    if (i < n4) split_one(s, dh + blockIdx.y * stride, dl + blockIdx.y * stride, i);
}

__global__ void k_split4(const float* __restrict__ s0, const float* __restrict__ s1,
                         const float* __restrict__ s2, const float* __restrict__ s3,
                         __half* __restrict__ dh, __half* __restrict__ dl,
                         size_t stride, int n4) {
    int i = blockIdx.x * blockDim.x + threadIdx.x;
    const float* sel[4] = {s0, s1, s2, s3};
    const float* s = sel[blockIdx.y];
    if (i < n4) split_one(s, dh + blockIdx.y * stride, dl + blockIdx.y * stride, i);
}

// fused bias-sum (blocks 0..31) + embedding split (blocks 32..)
__global__ void k_misc(const int* __restrict__ x, const float* __restrict__ emb,
                       __half* __restrict__ oh, __half* __restrict__ ol,
                       const float* __restrict__ a0, const float* __restrict__ b0,
                       const float* __restrict__ a1, const float* __restrict__ b1,
                       const float* __restrict__ a2, const float* __restrict__ b2,
                       const float* __restrict__ a3, const float* __restrict__ b3,
                       float* __restrict__ bs) {
    if (blockIdx.x < 32) {
        int i = blockIdx.x * 256 + threadIdx.x;      // 0..8191
        int job = i >> 11, e = i & 2047;
        const float* sa[4] = {a0, a1, a2, a3};
        const float* sb[4] = {b0, b1, b2, b3};
        bs[job * 2048 + e] = sa[job][e] + sb[job][e];
        return;
    }
    int chunk = (blockIdx.x - 32) * 256 + threadIdx.x;
    if (chunk < BS_ * (E_ / 4)) {
        int i = chunk >> 7;
        int j = chunk & 127;
        int tok = x[i];
        float4 v = ((const float4*)emb)[(size_t)tok * (E_ / 4) + j];
        __half h0 = __float2half(v.x), h1 = __float2half(v.y);
        __half h2 = __float2half(v.z), h3 = __float2half(v.w);
        __half2* dh = (__half2*)(oh + (size_t)i * E_ + j * 4);
        __half2* dl = (__half2*)(ol + (size_t)i * E_ + j * 4);
        dh[0] = __halves2half2(h0, h1);
        dh[1] = __halves2half2(h2, h3);
        dl[0] = __floats2half2_rn(v.x - __half2float(h0), v.y - __half2float(h1));
        dl[1] = __floats2half2_rn(v.z - __half2float(h2), v.w - __half2float(h3));
    }
}

// ---------------- 3-term split GEMM, 4-tile stages: C[16384,2048] ----------------
// C = Ah*Wh^T + Al*Wh^T + Ah*Wl^T. Stage loads {Ah,Al,Wh,Wl} once; 3 products per stage.
#define GBM 128
#define GBN 128
#define GBK 32
#define LDA 40
#define TSZ (GBM*LDA)        // 5120 halves per tile
#define STG4 (4*TSZ)         // 20480 halves
#define GSM3 (2*STG4*2)      // 81920 B

__device__ __forceinline__ void cpasync16(void* s, const void* g) {
    uint32_t sa = (uint32_t)__cvta_generic_to_shared(s);
    asm volatile("cp.async.cg.shared.global [%0], [%1], 16;\n" :: "r"(sa), "l"(g));
}

__global__ __launch_bounds__(256) void k_gemm(const __half* __restrict__ Ah,
                                              const __half* __restrict__ Al,
                                              const __half* __restrict__ Wh,
                                              const __half* __restrict__ Wl,
                                              float* __restrict__ C, int K) {
    extern __shared__ __half gsm[];
    int tid = threadIdx.x;
    int bm = blockIdx.y, bn = blockIdx.x;
    int wid = tid >> 5;
    int wm = wid & 3;        // 4 m-rows of 32
    int wn = wid >> 2;       // 2 n-cols of 64

    wmma::fragment<wmma::accumulator, 16, 16, 16, float> acc[2][4];
    #pragma unroll
    for (int i = 0; i < 2; i++)
        #pragma unroll
        for (int j = 0; j < 4; j++) wmma::fill_fragment(acc[i][j], 0.f);

    int NT = K / GBK;

    auto issue = [&](int kt) {
        const __half* s0 = Ah + (size_t)(bm * GBM) * K + kt * GBK;
        const __half* s1 = Al + (size_t)(bm * GBM) * K + kt * GBK;
        const __half* s2 = Wh + (size_t)(bn * GBN) * K + kt * GBK;
        const __half* s3 = Wl + (size_t)(bn * GBN) * K + kt * GBK;
        __half* dst = gsm + (kt & 1) * STG4;
        #pragma unroll
        for (int j = 0; j < 8; j++) {
            int c = tid + j * 256;           // 0..2047
            int tsel = c >> 9;               // 0:Ah 1:Al 2:Wh 3:Wl
            int cw = c & 511;
            int row = cw >> 2, cc = (cw & 3) * 8;
            const __half* s = (tsel == 0) ? s0 : (tsel == 1) ? s1 : (tsel == 2) ? s2 : s3;
            cpasync16(dst + tsel * TSZ + row * LDA + cc, s + (size_t)row * K + cc);
        }
        asm volatile("cp.async.commit_group;\n");
    };

    issue(0);

    for (int kt = 0; kt < NT; kt++) {
        if (kt + 1 < NT) {
            issue(kt + 1);
            asm volatile("cp.async.wait_group 1;\n");
        } else {
            asm volatile("cp.async.wait_group 0;\n");
        }
        __syncthreads();
        const __half* Ahs = gsm + (kt & 1) * STG4;
        const __half* Als = Ahs + TSZ;
        const __half* Whs = Ahs + 2 * TSZ;
        const __half* Wls = Ahs + 3 * TSZ;
        #pragma unroll
        for (int kk = 0; kk < 2; kk++) {
            wmma::fragment<wmma::matrix_a, 16, 16, 16, __half, wmma::row_major> afh[2], afl[2];
            #pragma unroll
            for (int i = 0; i < 2; i++) {
                wmma::load_matrix_sync(afh[i], Ahs + (wm * 32 + i * 16) * LDA + kk * 16, LDA);
                wmma::load_matrix_sync(afl[i], Als + (wm * 32 + i * 16) * LDA + kk * 16, LDA);
            }
            #pragma unroll
            for (int j = 0; j < 4; j++) {
                wmma::fragment<wmma::matrix_b, 16, 16, 16, __half, wmma::col_major> bfh, bfl;
                wmma::load_matrix_sync(bfh, Whs + (wn * 64 + j * 16) * LDA + kk * 16, LDA);
                wmma::load_matrix_sync(bfl, Wls + (wn * 64 + j * 16) * LDA + kk * 16, LDA);
                #pragma unroll
                for (int i = 0; i < 2; i++) {
                    wmma::mma_sync(acc[i][j], afh[i], bfh, acc[i][j]);
                    wmma::mma_sync(acc[i][j], afl[i], bfh, acc[i][j]);
                    wmma::mma_sync(acc[i][j], afh[i], bfl, acc[i][j]);
                }
            }
        }
        __syncthreads();
    }

    #pragma unroll
    for (int i = 0; i < 2; i++)
        #pragma unroll
        for (int j = 0; j < 4; j++) {
            int row = bm * GBM + wm * 32 + i * 16;
            int col = bn * GBN + wn * 64 + j * 16;
            wmma::store_matrix_sync(C + (size_t)row * G4H + col, acc[i][j], G4H,
                                    wmma::mem_row_major);
        }
}

// ---------------- persistent bidirectional LSTM recurrence ----------------
#define RNB 128
#define DNB 64               // CTAs per direction
#define LDH 520
#define LDGS 36
#define RECSM (3*32*LDH*2 + 32*LDGS*4)

// R3-proven single-counter barrier, one independent instance per direction.
// Reset is ATOMIC (atomicExch) by the releasing CTA before the gen increment.
__device__ __forceinline__ void gridbar(int dir) {
    __syncthreads();
    if (threadIdx.x == 0) {
        volatile unsigned* vg = &g_bar_gen[dir * 32];
        unsigned gen = *vg;
        __threadfence();
        unsigned t = atomicAdd(&g_bar_cnt[dir * 32], 1u);
        if (t == DNB - 1) {
            atomicExch(&g_bar_cnt[dir * 32], 0u);
            __threadfence();
            atomicAdd((unsigned*)&g_bar_gen[dir * 32], 1u);
        } else {
            while (*vg == gen) { }
        }
        __threadfence();
    }
    __syncthreads();
}

__device__ __forceinline__ float sigmoidf_(float x) { return 1.f / (1.f + __expf(-x)); }
__device__ __forceinline__ float tanhf_(float x) {
    x = fminf(fmaxf(x, -15.f), 15.f);
    float e = __expf(2.f * x);
    return (e - 1.f) / (e + 1.f);
}

__global__ __launch_bounds__(128) void k_rec(const float* __restrict__ xpf,
                                             const float* __restrict__ xpb,
                                             const __half* __restrict__ Whf_h,
                                             const __half* __restrict__ Whf_l,
                                             const __half* __restrict__ Whb_h,
                                             const __half* __restrict__ Whb_l,
                                             const float* __restrict__ bsf,
                                             const float* __restrict__ bsb,
                                             __half* __restrict__ yh,
                                             __half* __restrict__ yl) {
    extern __shared__ char smraw[];
    __half* Wlo = (__half*)smraw;
    __half* Hhi = (__half*)(smraw + 32 * LDH * 2);
    __half* Hlo = (__half*)(smraw + 2 * 32 * LDH * 2);
    float*  Gs  = (float*)(smraw + 3 * 32 * LDH * 2);

    int tid = threadIdx.x;
    int blk = blockIdx.x;
    int dir = blk >> 6;
    int grp = blk & 63;
    int ub  = grp * 8;
    const __half* Wh_h = dir ? Whb_h : Whf_h;
    const __half* Wh_l = dir ? Whb_l : Whf_l;
    const float*  xp   = dir ? xpb : xpf;
    const float*  bs   = dir ? bsb : bsf;

    for (int chunk = tid; chunk < 32 * 64; chunk += 128) {
        int c = chunk >> 6, w8 = (chunk & 63) * 8;
        int q = c >> 3, u = c & 7;
        uint4 v = *(const uint4*)(Wh_h + (size_t)(q * H_ + ub + u) * H_ + w8);
        *(uint4*)(Hhi + c * LDH + w8) = v;
    }

    float bias[2][4];
    float cst[2] = {0.f, 0.f};
    #pragma unroll
    for (int j = 0; j < 2; j++) {
        int it = tid + 128 * j;
        int b = it >> 3, u = it & 7;
        #pragma unroll
        for (int q = 0; q < 4; q++) bias[j][q] = bs[q * H_ + ub + u];
        __stcg((unsigned short*)&g_hbh[(0 * 2 + dir) * BH_ + b * H_ + ub + u], (unsigned short)0);
        __stcg((unsigned short*)&g_hbl[(0 * 2 + dir) * BH_ + b * H_ + ub + u], (unsigned short)0);
    }
    __syncthreads();

    int wid = tid >> 5;
    int mi = wid & 1;
    int ni = wid >> 1;
    wmma::fragment<wmma::matrix_b, 16, 16, 16, __half, wmma::col_major> bfr[32];
    #pragma unroll
    for (int kk = 0; kk < 32; kk++)
        wmma::load_matrix_sync(bfr[kk], Hhi + (ni * 16) * LDH + kk * 16, LDH);
    __syncthreads();

    for (int chunk = tid; chunk < 32 * 64; chunk += 128) {
        int c = chunk >> 6, w8 = (chunk & 63) * 8;
        int q = c >> 3, u = c & 7;
        uint4 v = *(const uint4*)(Wh_l + (size_t)(q * H_ + ub + u) * H_ + w8);
        *(uint4*)(Wlo + c * LDH + w8) = v;
    }

    __threadfence();          // release h zero-init (all threads)
    gridbar(dir);

    for (int s = 0; s < S_; s++) {
        int p = s & 1;

        // prefetch this step's xp rows early (independent of h)
        int t = dir ? (S_ - 1 - s) : s;
        float px[2][4];
        #pragma unroll
        for (int j = 0; j < 2; j++) {
            int it = tid + 128 * j;
            int b = it >> 3, u = it & 7;
            const float* xr = xp + (size_t)(b * S_ + t) * G4H + ub + u;
            px[j][0] = __ldg(xr);
            px[j][1] = __ldg(xr + 512);
            px[j][2] = __ldg(xr + 1024);
            px[j][3] = __ldg(xr + 1536);
        }

        const __half* hsh = &g_hbh[(p * 2 + dir) * BH_];
        const __half* hsl = &g_hbl[(p * 2 + dir) * BH_];
        for (int chunk = tid; chunk < 32 * 64; chunk += 128) {
            int b = chunk >> 6, w8 = (chunk & 63) * 8;
            uint4 vh = __ldcg((const uint4*)(hsh + b * H_ + w8));
            uint4 vl = __ldcg((const uint4*)(hsl + b * H_ + w8));
            *(uint4*)(Hhi + b * LDH + w8) = vh;
            *(uint4*)(Hlo + b * LDH + w8) = vl;
        }
        __syncthreads();

        // 3 independent accumulator chains (hi*hi, lo*hi, hi*lo) -> issue-bound,
        // not latency-bound; merged elementwise afterward (fp32, same math).
        wmma::fragment<wmma::accumulator, 16, 16, 16, float> acc0, acc1, acc2;
        wmma::fill_fragment(acc0, 0.f);
        wmma::fill_fragment(acc1, 0.f);
        wmma::fill_fragment(acc2, 0.f);
        #pragma unroll
        for (int kk = 0; kk < 32; kk++) {
            wmma::fragment<wmma::matrix_a, 16, 16, 16, __half, wmma::row_major> ah, al;
            wmma::fragment<wmma::matrix_b, 16, 16, 16, __half, wmma::col_major> bl;
            wmma::load_matrix_sync(ah, Hhi + (mi * 16) * LDH + kk * 16, LDH);
            wmma::load_matrix_sync(al, Hlo + (mi * 16) * LDH + kk * 16, LDH);
            wmma::load_matrix_sync(bl, Wlo + (ni * 16) * LDH + kk * 16, LDH);
            wmma::mma_sync(acc0, ah, bfr[kk], acc0);
            wmma::mma_sync(acc1, al, bfr[kk], acc1);
            wmma::mma_sync(acc2, ah, bl, acc2);
        }
        #pragma unroll
        for (int e = 0; e < acc0.num_elements; e++)
            acc0.x[e] += acc1.x[e] + acc2.x[e];
        wmma::store_matrix_sync(Gs + (mi * 16) * LDGS + ni * 16, acc0, LDGS, wmma::mem_row_major);
        __syncthreads();

        #pragma unroll
        for (int j = 0; j < 2; j++) {
            int it = tid + 128 * j;
            int b = it >> 3, u = it & 7;
            float gi = Gs[b * LDGS + u]       + px[j][0] + bias[j][0];
            float gf = Gs[b * LDGS + 8 + u]   + px[j][1] + bias[j][1];
            float gg = Gs[b * LDGS + 16 + u]  + px[j][2] + bias[j][2];
            float go = Gs[b * LDGS + 24 + u]  + px[j][3] + bias[j][3];
            float cc = sigmoidf_(gf) * cst[j] + sigmoidf_(gi) * tanhf_(gg);
            cst[j] = cc;
            float h = sigmoidf_(go) * tanhf_(cc);
            __half hh = __float2half(h);
            __half hl = __float2half(h - __half2float(hh));
            int ho = ((p ^ 1) * 2 + dir) * BH_ + b * H_ + ub + u;
            __stcg((unsigned short*)&g_hbh[ho], __half_as_ushort(hh));
            __stcg((unsigned short*)&g_hbl[ho], __half_as_ushort(hl));
            size_t yo = (size_t)(b * S_ + t) * (2 * H_) + dir * H_ + ub + u;
            yh[yo] = hh;
            yl[yo] = hl;
        }
        __threadfence();      // release this step's h stores (all threads)
        gridbar(dir);
    }
}

// ---------------- pooling partials + FC ----------------
__global__ __launch_bounds__(256) void k_ppart(const __half* __restrict__ yh,
                                               const __half* __restrict__ yl,
                                               const int* __restrict__ mask,
                                               float* __restrict__ pool,
                                               float* __restrict__ cntp) {
    int b = blockIdx.x, sc = blockIdx.y, tid = threadIdx.x;
    float acc[4] = {0.f, 0.f, 0.f, 0.f};
    float mcount = 0.f;
    for (int ss = 0; ss < 64; ss++) {
        int s = sc * 64 + ss;
        float m = (float)mask[b * S_ + s];
        mcount += m;
        const __half* yrh = yh + (size_t)(b * S_ + s) * 1024;
        const __half* yrl = yl + (size_t)(b * S_ + s) * 1024;
        #pragma unroll
        for (int j = 0; j < 4; j++) {
            int k = tid + j * 256;
            acc[j] += m * (__half2float(yrh[k]) + __half2float(yrl[k]));
        }
    }
    float* prow = pool + (size_t)(b * 8 + sc) * 1024;
    #pragma unroll
    for (int j = 0; j < 4; j++) prow[tid + j * 256] = acc[j];
    if (tid == 0) cntp[b * 8 + sc] = mcount;
}

__global__ __launch_bounds__(256) void k_fc(const float* __restrict__ pool,
                                            const float* __restrict__ cntp,
                                            const float* __restrict__ fcW,
                                            const float* __restrict__ fcb,
                                            float* __restrict__ out) {
    int b = blockIdx.x, tid = threadIdx.x;
    __shared__ float red[256];
    float cnt = 0.f;
    #pragma unroll
    for (int p = 0; p < 8; p++) cnt += cntp[b * 8 + p];
    float inv = 1.f / fmaxf(cnt, 1e-9f);
    float pooled[4];
    #pragma unroll
    for (int j = 0; j < 4; j++) {
        int col = tid + j * 256;
        float sum = 0.f;
        #pragma unroll
        for (int p = 0; p < 8; p++) sum += pool[(size_t)(b * 8 + p) * 1024 + col];
        pooled[j] = sum * inv;
    }
    for (int c = 0; c < 2; c++) {
        float pv = 0.f;
        #pragma unroll
        for (int j = 0; j < 4; j++) {
            int k = tid + j * 256;
            pv += pooled[j] * fcW[c * 1024 + k];
        }
        red[tid] = pv;
        __syncthreads();
        for (int st = 128; st > 0; st >>= 1) {
            if (tid < st) red[tid] += red[tid + st];
            __syncthreads();
        }
        if (tid == 0) out[b * 2 + c] = red[0] + fcb[c];
        __syncthreads();
    }
}

// ---------------- host orchestration ----------------
extern "C" void kernel_launch(void* const* d_in, const int* in_sizes, int n_in,
                              void* d_out, int out_size) {
    const int*   x   = (const int*)d_in[0];
    const int*   am  = (const int*)d_in[1];
    const float* emb = (const float*)d_in[2];
    const float* fcW = (const float*)d_in[3];
    const float* fcb = (const float*)d_in[4];
    const float* Wih[2][2] = {{(const float*)d_in[5],  (const float*)d_in[9]},
                              {(const float*)d_in[13], (const float*)d_in[17]}};
    const float* Whh[2][2] = {{(const float*)d_in[6],  (const float*)d_in[10]},
                              {(const float*)d_in[14], (const float*)d_in[18]}};
    const float* bih[2][2] = {{(const float*)d_in[7],  (const float*)d_in[11]},
                              {(const float*)d_in[15], (const float*)d_in[19]}};
    const float* bhh[2][2] = {{(const float*)d_in[8],  (const float*)d_in[12]},
                              {(const float*)d_in[16], (const float*)d_in[20]}};

    void *pX0h, *pX0l, *py0h, *py0l, *py1h, *py1l, *pxp0, *pxp1;
    void *pWihH, *pWihL, *pWhhH, *pWhhL, *pbs, *ppool, *pcnt;
    cudaGetSymbolAddress(&pX0h, g_X0h);
    cudaGetSymbolAddress(&pX0l, g_X0l);
    cudaGetSymbolAddress(&py0h, g_y0h);
    cudaGetSymbolAddress(&py0l, g_y0l);
    cudaGetSymbolAddress(&py1h, g_y1h);
    cudaGetSymbolAddress(&py1l, g_y1l);
    cudaGetSymbolAddress(&pxp0, g_xp0);
    cudaGetSymbolAddress(&pxp1, g_xp1);
    cudaGetSymbolAddress(&pWihH, g_Wih_h);
    cudaGetSymbolAddress(&pWihL, g_Wih_l);
    cudaGetSymbolAddress(&pWhhH, g_Whh_h);
    cudaGetSymbolAddress(&pWhhL, g_Whh_l);
    cudaGetSymbolAddress(&pbs,  g_bsum);
    cudaGetSymbolAddress(&ppool, g_pool);
    cudaGetSymbolAddress(&pcnt,  g_cntp);

    cudaFuncSetAttribute(k_rec,  cudaFuncAttributeMaxDynamicSharedMemorySize, RECSM);
    cudaFuncSetAttribute(k_gemm, cudaFuncAttributeMaxDynamicSharedMemorySize, GSM3);

    const size_t WIH_STRIDE = (size_t)G4H * 1024;
    const size_t WHH_STRIDE = (size_t)G4H * H_;

    // prep (4 launches)
    {
        int n4 = G4H * E_ / 4;
        k_split2<<<dim3((n4 + 255) / 256, 2), 256>>>(Wih[0][0], Wih[0][1],
                                                     (__half*)pWihH, (__half*)pWihL,
                                                     WIH_STRIDE, n4);
        int n4b = G4H * 1024 / 4;
        k_split2<<<dim3((n4b + 255) / 256, 2), 256>>>(Wih[1][0], Wih[1][1],
                                                      (__half*)pWihH + 2 * WIH_STRIDE,
                                                      (__half*)pWihL + 2 * WIH_STRIDE,
                                                      WIH_STRIDE, n4b);
        int n4h = G4H * H_ / 4;
        k_split4<<<dim3((n4h + 255) / 256, 4), 256>>>(Whh[0][0], Whh[0][1], Whh[1][0], Whh[1][1],
                                                      (__half*)pWhhH, (__half*)pWhhL,
                                                      WHH_STRIDE, n4h);
        k_misc<<<32 + (BS_ * (E_ / 4) + 255) / 256, 256>>>(
            x, emb, (__half*)pX0h, (__half*)pX0l,
            bih[0][0], bhh[0][0], bih[0][1], bhh[0][1],
            bih[1][0], bhh[1][0], bih[1][1], bhh[1][1], (float*)pbs);
    }

    dim3 gg(G4H / GBN, BS_ / GBM);   // (16, 128)

    // ----- layer 0 -----
    k_gemm<<<gg, 256, GSM3>>>((const __half*)pX0h, (const __half*)pX0l,
                              (const __half*)pWihH + 0 * WIH_STRIDE,
                              (const __half*)pWihL + 0 * WIH_STRIDE, (float*)pxp0, E_);
    k_gemm<<<gg, 256, GSM3>>>((const __half*)pX0h, (const __half*)pX0l,
                              (const __half*)pWihH + 1 * WIH_STRIDE,
                              (const __half*)pWihL + 1 * WIH_STRIDE, (float*)pxp1, E_);
    k_rec<<<RNB, 128, RECSM>>>((const float*)pxp0, (const float*)pxp1,
                               (const __half*)pWhhH + 0 * WHH_STRIDE,
                               (const __half*)pWhhL + 0 * WHH_STRIDE,
                               (const __half*)pWhhH + 1 * WHH_STRIDE,
                               (const __half*)pWhhL + 1 * WHH_STRIDE,
                               (const float*)pbs + 0 * G4H, (const float*)pbs + 1 * G4H,
                               (__half*)py0h, (__half*)py0l);

    // ----- layer 1 -----
    k_gemm<<<gg, 256, GSM3>>>((const __half*)py0h, (const __half*)py0l,
                              (const __half*)pWihH + 2 * WIH_STRIDE,
                              (const __half*)pWihL + 2 * WIH_STRIDE, (float*)pxp0, 2 * H_);
    k_gemm<<<gg, 256, GSM3>>>((const __half*)py0h, (const __half*)py0l,
                              (const __half*)pWihH + 3 * WIH_STRIDE,
                              (const __half*)pWihL + 3 * WIH_STRIDE, (float*)pxp1, 2 * H_);
    k_rec<<<RNB, 128, RECSM>>>((const float*)pxp0, (const float*)pxp1,
                               (const __half*)pWhhH + 2 * WHH_STRIDE,
                               (const __half*)pWhhL + 2 * WHH_STRIDE,
                               (const __half*)pWhhH + 3 * WHH_STRIDE,
                               (const __half*)pWhhL + 3 * WHH_STRIDE,
                               (const float*)pbs + 2 * G4H, (const float*)pbs + 3 * G4H,
                               (__half*)py1h, (__half*)py1l);

    // ----- pool + fc -----
    k_ppart<<<dim3(32, 8), 256>>>((const __half*)py1h, (const __half*)py1l, am,
                                  (float*)ppool, (float*)pcnt);
    k_fc<<<32, 256>>>((const float*)ppool, (const float*)pcnt, fcW, fcb, (float*)d_out);
}

// round 16
// speedup vs baseline: 1.0625x; 1.0293x over previous
#include <cuda_runtime.h>
#include <cuda_fp16.h>
#include <mma.h>
#include <stdint.h>

using namespace nvcuda;

#define B_   32
#define S_   512
#define H_   512
#define E_   512
#define G4H  2048
#define BS_  (B_*S_)          // 16384
#define BH_  (B_*H_)          // 16384

// ---------------- scratch (__device__ globals; no allocation allowed) ----------------
__device__ __half g_X0h[BS_*E_];
__device__ __half g_X0l[BS_*E_];
__device__ __half g_y0h[BS_*2*H_];
__device__ __half g_y0l[BS_*2*H_];
__device__ __half g_y1h[BS_*2*H_];
__device__ __half g_y1l[BS_*2*H_];
__device__ float  g_xp0[(size_t)BS_*G4H];
__device__ float  g_xp1[(size_t)BS_*G4H];
__device__ __half g_Wih_h[2*2*(size_t)G4H*1024];   // [layer][dir], K up to 1024
__device__ __half g_Wih_l[2*2*(size_t)G4H*1024];
__device__ __half g_Whh_h[2*2*(size_t)G4H*H_];
__device__ __half g_Whh_l[2*2*(size_t)G4H*H_];
__device__ float  g_bsum[2*2*G4H];
__device__ __half g_hbh[2*2*BH_];
__device__ __half g_hbl[2*2*BH_];
__device__ float  g_pool[32*8*1024];
__device__ float  g_cntp[32*8];
// per-direction barrier state (R3-proven protocol, one instance per direction,
// instances 128B apart -> distinct L2 lines)
__device__ unsigned g_bar_cnt[2*32];
__device__ unsigned g_bar_gen[2*32];

// ---------------- fused prep kernel (1 launch) ----------------
__device__ __forceinline__ void split_one(const float* __restrict__ src,
                                          __half* __restrict__ dh,
                                          __half* __restrict__ dl, int i) {
    float4 v = ((const float4*)src)[i];
    __half h0 = __float2half(v.x), h1 = __float2half(v.y);
    __half h2 = __float2half(v.z), h3 = __float2half(v.w);
    __half2* dhp = (__half2*)(dh + (size_t)i * 4);
    __half2* dlp = (__half2*)(dl + (size_t)i * 4);
    dhp[0] = __halves2half2(h0, h1);
    dhp[1] = __halves2half2(h2, h3);
    dlp[0] = __floats2half2_rn(v.x - __half2float(h0), v.y - __half2float(h1));
    dlp[1] = __floats2half2_rn(v.z - __half2float(h2), v.w - __half2float(h3));
}

#define WIHS ((size_t)G4H*1024)     // Wih dest stride (halves)
#define WHHS ((size_t)G4H*H_)       // Whh dest stride (halves)
// range boundaries (in work items)
#define PR_A 524288L                 // Wih L0: 2 dirs x 262144 float4
#define PR_B 1572864L                // Wih L1: 2 dirs x 524288 float4
#define PR_C 2621440L                // Whh:    4     x 262144 float4
#define PR_D 2629632L                // bias:   8192 floats
#define PR_E 4726784L                // embed:  2097152 chunks
#define PR_BLOCKS 18464              // ceil(PR_E / 256)

__global__ void k_prep(const int* __restrict__ x, const float* __restrict__ emb,
                       __half* __restrict__ Xh, __half* __restrict__ Xl,
                       const float* __restrict__ wiL0f, const float* __restrict__ wiL0b,
                       const float* __restrict__ wiL1f, const float* __restrict__ wiL1b,
                       const float* __restrict__ wh0, const float* __restrict__ wh1,
                       const float* __restrict__ wh2, const float* __restrict__ wh3,
                       __half* __restrict__ WihH, __half* __restrict__ WihL,
                       __half* __restrict__ WhhH, __half* __restrict__ WhhL,
                       const float* __restrict__ bi0, const float* __restrict__ bh0,
                       const float* __restrict__ bi1, const float* __restrict__ bh1,
                       const float* __restrict__ bi2, const float* __restrict__ bh2,
                       const float* __restrict__ bi3, const float* __restrict__ bh3,
                       float* __restrict__ bs) {
    long i = (long)blockIdx.x * 256 + threadIdx.x;
    if (i < PR_A) {
        int d = (int)(i >> 18);                  // /262144
        int j = (int)(i & 262143);
        split_one(d ? wiL0b : wiL0f, WihH + d * WIHS, WihL + d * WIHS, j);
    } else if (i < PR_B) {
        long k = i - PR_A;
        int d = (int)(k >> 19);                  // /524288
        int j = (int)(k & 524287);
        split_one(d ? wiL1b : wiL1f, WihH + (2 + d) * WIHS, WihL + (2 + d) * WIHS, j);
    } else if (i < PR_C) {
        long k = i - PR_B;
        int q = (int)(k >> 18);                  // 0..3
        int j = (int)(k & 262143);
        const float* src = (q == 0) ? wh0 : (q == 1) ? wh1 : (q == 2) ? wh2 : wh3;
        split_one(src, WhhH + q * WHHS, WhhL + q * WHHS, j);
    } else if (i < PR_D) {
        int k = (int)(i - PR_C);                 // 0..8191
        int job = k >> 11, e = k & 2047;
        const float* sa = (job == 0) ? bi0 : (job == 1) ? bi1 : (job == 2) ? bi2 : bi3;
        const float* sb = (job == 0) ? bh0 : (job == 1) ? bh1 : (job == 2) ? bh2 : bh3;
        bs[job * 2048 + e] = sa[e] + sb[e];
    } else if (i < PR_E) {
        long chunk = i - PR_D;                   // 0..2097151
        int t = (int)(chunk >> 7);               // token index
        int j = (int)(chunk & 127);
        int tok = x[t];
        float4 v = ((const float4*)emb)[(size_t)tok * (E_ / 4) + j];
        __half h0 = __float2half(v.x), h1 = __float2half(v.y);
        __half h2 = __float2half(v.z), h3 = __float2half(v.w);
        __half2* dh = (__half2*)(Xh + (size_t)t * E_ + j * 4);
        __half2* dl = (__half2*)(Xl + (size_t)t * E_ + j * 4);
        dh[0] = __halves2half2(h0, h1);
        dh[1] = __halves2half2(h2, h3);
        dl[0] = __floats2half2_rn(v.x - __half2float(h0), v.y - __half2float(h1));
        dl[1] = __floats2half2_rn(v.z - __half2float(h2), v.w - __half2float(h3));
    }
}

// ---------------- 3-term split GEMM, 4-tile stages: C[16384,2048] ----------------
// C = Ah*Wh^T + Al*Wh^T + Ah*Wl^T. Stage loads {Ah,Al,Wh,Wl} once; 3 products per stage.
#define GBM 128
#define GBN 128
#define GBK 32
#define LDA 40
#define TSZ (GBM*LDA)        // 5120 halves per tile
#define STG4 (4*TSZ)         // 20480 halves
#define GSM3 (2*STG4*2)      // 81920 B

__device__ __forceinline__ void cpasync16(void* s, const void* g) {
    uint32_t sa = (uint32_t)__cvta_generic_to_shared(s);
    asm volatile("cp.async.cg.shared.global [%0], [%1], 16;\n" :: "r"(sa), "l"(g));
}

__global__ __launch_bounds__(256) void k_gemm(const __half* __restrict__ Ah,
                                              const __half* __restrict__ Al,
                                              const __half* __restrict__ Wh,
                                              const __half* __restrict__ Wl,
                                              float* __restrict__ C, int K) {
    extern __shared__ __half gsm[];
    int tid = threadIdx.x;
    int bm = blockIdx.y, bn = blockIdx.x;
    int wid = tid >> 5;
    int wm = wid & 3;        // 4 m-rows of 32
    int wn = wid >> 2;       // 2 n-cols of 64

    wmma::fragment<wmma::accumulator, 16, 16, 16, float> acc[2][4];
    #pragma unroll
    for (int i = 0; i < 2; i++)
        #pragma unroll
        for (int j = 0; j < 4; j++) wmma::fill_fragment(acc[i][j], 0.f);

    int NT = K / GBK;

    auto issue = [&](int kt) {
        const __half* s0 = Ah + (size_t)(bm * GBM) * K + kt * GBK;
        const __half* s1 = Al + (size_t)(bm * GBM) * K + kt * GBK;
        const __half* s2 = Wh + (size_t)(bn * GBN) * K + kt * GBK;
        const __half* s3 = Wl + (size_t)(bn * GBN) * K + kt * GBK;
        __half* dst = gsm + (kt & 1) * STG4;
        #pragma unroll
        for (int j = 0; j < 8; j++) {
            int c = tid + j * 256;           // 0..2047
            int tsel = c >> 9;               // 0:Ah 1:Al 2:Wh 3:Wl
            int cw = c & 511;
            int row = cw >> 2, cc = (cw & 3) * 8;
            const __half* s = (tsel == 0) ? s0 : (tsel == 1) ? s1 : (tsel == 2) ? s2 : s3;
            cpasync16(dst + tsel * TSZ + row * LDA + cc, s + (size_t)row * K + cc);
        }
        asm volatile("cp.async.commit_group;\n");
    };

    issue(0);

    for (int kt = 0; kt < NT; kt++) {
        if (kt + 1 < NT) {
            issue(kt + 1);
            asm volatile("cp.async.wait_group 1;\n");
        } else {
            asm volatile("cp.async.wait_group 0;\n");
        }
        __syncthreads();
        const __half* Ahs = gsm + (kt & 1) * STG4;
        const __half* Als = Ahs + TSZ;
        const __half* Whs = Ahs + 2 * TSZ;
        const __half* Wls = Ahs + 3 * TSZ;
        #pragma unroll
        for (int kk = 0; kk < 2; kk++) {
            wmma::fragment<wmma::matrix_a, 16, 16, 16, __half, wmma::row_major> afh[2], afl[2];
            #pragma unroll
            for (int i = 0; i < 2; i++) {
                wmma::load_matrix_sync(afh[i], Ahs + (wm * 32 + i * 16) * LDA + kk * 16, LDA);
                wmma::load_matrix_sync(afl[i], Als + (wm * 32 + i * 16) * LDA + kk * 16, LDA);
            }
            #pragma unroll
            for (int j = 0; j < 4; j++) {
                wmma::fragment<wmma::matrix_b, 16, 16, 16, __half, wmma::col_major> bfh, bfl;
                wmma::load_matrix_sync(bfh, Whs + (wn * 64 + j * 16) * LDA + kk * 16, LDA);
                wmma::load_matrix_sync(bfl, Wls + (wn * 64 + j * 16) * LDA + kk * 16, LDA);
                #pragma unroll
                for (int i = 0; i < 2; i++) {
                    wmma::mma_sync(acc[i][j], afh[i], bfh, acc[i][j]);
                    wmma::mma_sync(acc[i][j], afl[i], bfh, acc[i][j]);
                    wmma::mma_sync(acc[i][j], afh[i], bfl, acc[i][j]);
                }
            }
        }
        __syncthreads();
    }

    #pragma unroll
    for (int i = 0; i < 2; i++)
        #pragma unroll
        for (int j = 0; j < 4; j++) {
            int row = bm * GBM + wm * 32 + i * 16;
            int col = bn * GBN + wn * 64 + j * 16;
            wmma::store_matrix_sync(C + (size_t)row * G4H + col, acc[i][j], G4H,
                                    wmma::mem_row_major);
        }
}

// ---------------- persistent bidirectional LSTM recurrence ----------------
#define RNB 128
#define DNB 64               // CTAs per direction
#define LDH 520
#define LDGS 36
#define RECSM (3*32*LDH*2 + 32*LDGS*4)

// R3-proven single-counter barrier, one independent instance per direction.
// Reset is ATOMIC (atomicExch) by the releasing CTA before the gen increment.
__device__ __forceinline__ void gridbar(int dir) {
    __syncthreads();
    if (threadIdx.x == 0) {
        volatile unsigned* vg = &g_bar_gen[dir * 32];
        unsigned gen = *vg;
        __threadfence();
        unsigned t = atomicAdd(&g_bar_cnt[dir * 32], 1u);
        if (t == DNB - 1) {
            atomicExch(&g_bar_cnt[dir * 32], 0u);
            __threadfence();
            atomicAdd((unsigned*)&g_bar_gen[dir * 32], 1u);
        } else {
            while (*vg == gen) { }
        }
        __threadfence();
    }
    __syncthreads();
}

__device__ __forceinline__ float sigmoidf_(float x) { return 1.f / (1.f + __expf(-x)); }
__device__ __forceinline__ float tanhf_(float x) {
    x = fminf(fmaxf(x, -15.f), 15.f);
    float e = __expf(2.f * x);
    return (e - 1.f) / (e + 1.f);
}

__global__ __launch_bounds__(128) void k_rec(const float* __restrict__ xpf,
                                             const float* __restrict__ xpb,
                                             const __half* __restrict__ Whf_h,
                                             const __half* __restrict__ Whf_l,
                                             const __half* __restrict__ Whb_h,
                                             const __half* __restrict__ Whb_l,
                                             const float* __restrict__ bsf,
                                             const float* __restrict__ bsb,
                                             __half* __restrict__ yh,
                                             __half* __restrict__ yl) {
    extern __shared__ char smraw[];
    __half* Wlo = (__half*)smraw;
    __half* Hhi = (__half*)(smraw + 32 * LDH * 2);
    __half* Hlo = (__half*)(smraw + 2 * 32 * LDH * 2);
    float*  Gs  = (float*)(smraw + 3 * 32 * LDH * 2);

    int tid = threadIdx.x;
    int blk = blockIdx.x;
    int dir = blk >> 6;
    int grp = blk & 63;
    int ub  = grp * 8;
    const __half* Wh_h = dir ? Whb_h : Whf_h;
    const __half* Wh_l = dir ? Whb_l : Whf_l;
    const float*  xp   = dir ? xpb : xpf;
    const float*  bs   = dir ? bsb : bsf;

    for (int chunk = tid; chunk < 32 * 64; chunk += 128) {
        int c = chunk >> 6, w8 = (chunk & 63) * 8;
        int q = c >> 3, u = c & 7;
        uint4 v = *(const uint4*)(Wh_h + (size_t)(q * H_ + ub + u) * H_ + w8);
        *(uint4*)(Hhi + c * LDH + w8) = v;
    }

    float bias[2][4];
    float cst[2] = {0.f, 0.f};
    #pragma unroll
    for (int j = 0; j < 2; j++) {
        int it = tid + 128 * j;
        int b = it >> 3, u = it & 7;
        #pragma unroll
        for (int q = 0; q < 4; q++) bias[j][q] = bs[q * H_ + ub + u];
        __stcg((unsigned short*)&g_hbh[(0 * 2 + dir) * BH_ + b * H_ + ub + u], (unsigned short)0);
        __stcg((unsigned short*)&g_hbl[(0 * 2 + dir) * BH_ + b * H_ + ub + u], (unsigned short)0);
    }
    __syncthreads();

    int wid = tid >> 5;
    int mi = wid & 1;
    int ni = wid >> 1;
    wmma::fragment<wmma::matrix_b, 16, 16, 16, __half, wmma::col_major> bfr[32];
    #pragma unroll
    for (int kk = 0; kk < 32; kk++)
        wmma::load_matrix_sync(bfr[kk], Hhi + (ni * 16) * LDH + kk * 16, LDH);
    __syncthreads();

    for (int chunk = tid; chunk < 32 * 64; chunk += 128) {
        int c = chunk >> 6, w8 = (chunk & 63) * 8;
        int q = c >> 3, u = c & 7;
        uint4 v = *(const uint4*)(Wh_l + (size_t)(q * H_ + ub + u) * H_ + w8);
        *(uint4*)(Wlo + c * LDH + w8) = v;
    }

    // prefetch xp for step 0 (independent of h)
    float px[2][4];
    {
        int t0 = dir ? (S_ - 1) : 0;
        #pragma unroll
        for (int j = 0; j < 2; j++) {
            int it = tid + 128 * j;
            int b = it >> 3, u = it & 7;
            const float* xr = xp + (size_t)(b * S_ + t0) * G4H + ub + u;
            px[j][0] = __ldg(xr);
            px[j][1] = __ldg(xr + 512);
            px[j][2] = __ldg(xr + 1024);
            px[j][3] = __ldg(xr + 1536);
        }
    }

    __threadfence();          // release h zero-init (all threads)
    gridbar(dir);

    for (int s = 0; s < S_; s++) {
        int p = s & 1;
        int t = dir ? (S_ - 1 - s) : s;

        const __half* hsh = &g_hbh[(p * 2 + dir) * BH_];
        const __half* hsl = &g_hbl[(p * 2 + dir) * BH_];
        for (int chunk = tid; chunk < 32 * 64; chunk += 128) {
            int b = chunk >> 6, w8 = (chunk & 63) * 8;
            uint4 vh = __ldcg((const uint4*)(hsh + b * H_ + w8));
            uint4 vl = __ldcg((const uint4*)(hsl + b * H_ + w8));
            *(uint4*)(Hhi + b * LDH + w8) = vh;
            *(uint4*)(Hlo + b * LDH + w8) = vl;
        }
        __syncthreads();

        // 3 independent accumulator chains (hi*hi, lo*hi, hi*lo) -> issue-bound.
        wmma::fragment<wmma::accumulator, 16, 16, 16, float> acc0, acc1, acc2;
        wmma::fill_fragment(acc0, 0.f);
        wmma::fill_fragment(acc1, 0.f);
        wmma::fill_fragment(acc2, 0.f);
        #pragma unroll
        for (int kk = 0; kk < 32; kk++) {
            wmma::fragment<wmma::matrix_a, 16, 16, 16, __half, wmma::row_major> ah, al;
            wmma::fragment<wmma::matrix_b, 16, 16, 16, __half, wmma::col_major> bl;
            wmma::load_matrix_sync(ah, Hhi + (mi * 16) * LDH + kk * 16, LDH);
            wmma::load_matrix_sync(al, Hlo + (mi * 16) * LDH + kk * 16, LDH);
            wmma::load_matrix_sync(bl, Wlo + (ni * 16) * LDH + kk * 16, LDH);
            wmma::mma_sync(acc0, ah, bfr[kk], acc0);
            wmma::mma_sync(acc1, al, bfr[kk], acc1);
            wmma::mma_sync(acc2, ah, bl, acc2);
        }
        #pragma unroll
        for (int e = 0; e < acc0.num_elements; e++)
            acc0.x[e] += acc1.x[e] + acc2.x[e];
        wmma::store_matrix_sync(Gs + (mi * 16) * LDGS + ni * 16, acc0, LDGS, wmma::mem_row_major);
        __syncthreads();

        // issue next step's xp loads NOW: latency hides behind elementwise + barrier
        float pxn[2][4];
        if (s + 1 < S_) {
            int tn = dir ? (S_ - 2 - s) : (s + 1);
            #pragma unroll
            for (int j = 0; j < 2; j++) {
                int it = tid + 128 * j;
                int b = it >> 3, u = it & 7;
                const float* xr = xp + (size_t)(b * S_ + tn) * G4H + ub + u;
                pxn[j][0] = __ldg(xr);
                pxn[j][1] = __ldg(xr + 512);
                pxn[j][2] = __ldg(xr + 1024);
                pxn[j][3] = __ldg(xr + 1536);
            }
        }

        #pragma unroll
        for (int j = 0; j < 2; j++) {
            int it = tid + 128 * j;
            int b = it >> 3, u = it & 7;
            float gi = Gs[b * LDGS + u]       + px[j][0] + bias[j][0];
            float gf = Gs[b * LDGS + 8 + u]   + px[j][1] + bias[j][1];
            float gg = Gs[b * LDGS + 16 + u]  + px[j][2] + bias[j][2];
            float go = Gs[b * LDGS + 24 + u]  + px[j][3] + bias[j][3];
            float cc = sigmoidf_(gf) * cst[j] + sigmoidf_(gi) * tanhf_(gg);
            cst[j] = cc;
            float h = sigmoidf_(go) * tanhf_(cc);
            __half hh = __float2half(h);
            __half hl = __float2half(h - __half2float(hh));
            int ho = ((p ^ 1) * 2 + dir) * BH_ + b * H_ + ub + u;
            __stcg((unsigned short*)&g_hbh[ho], __half_as_ushort(hh));
            __stcg((unsigned short*)&g_hbl[ho], __half_as_ushort(hl));
            size_t yo = (size_t)(b * S_ + t) * (2 * H_) + dir * H_ + ub + u;
            yh[yo] = hh;
            yl[yo] = hl;
        }
        #pragma unroll
        for (int j = 0; j < 2; j++)
            #pragma unroll
            for (int q = 0; q < 4; q++) px[j][q] = pxn[j][q];

        __threadfence();      // release this step's h stores (all threads)
        gridbar(dir);
    }
}

// ---------------- pooling partials + FC ----------------
__global__ __launch_bounds__(256) void k_ppart(const __half* __restrict__ yh,
                                               const __half* __restrict__ yl,
                                               const int* __restrict__ mask,
                                               float* __restrict__ pool,
                                               float* __restrict__ cntp) {
    int b = blockIdx.x, sc = blockIdx.y, tid = threadIdx.x;
    float acc[4] = {0.f, 0.f, 0.f, 0.f};
    float mcount = 0.f;
    for (int ss = 0; ss < 64; ss++) {
        int s = sc * 64 + ss;
        float m = (float)mask[b * S_ + s];
        mcount += m;
        const __half* yrh = yh + (size_t)(b * S_ + s) * 1024;
        const __half* yrl = yl + (size_t)(b * S_ + s) * 1024;
        #pragma unroll
        for (int j = 0; j < 4; j++) {
            int k = tid + j * 256;
            acc[j] += m * (__half2float(yrh[k]) + __half2float(yrl[k]));
        }
    }
    float* prow = pool + (size_t)(b * 8 + sc) * 1024;
    #pragma unroll
    for (int j = 0; j < 4; j++) prow[tid + j * 256] = acc[j];
    if (tid == 0) cntp[b * 8 + sc] = mcount;
}

__global__ __launch_bounds__(256) void k_fc(const float* __restrict__ pool,
                                            const float* __restrict__ cntp,
                                            const float* __restrict__ fcW,
                                            const float* __restrict__ fcb,
                                            float* __restrict__ out) {
    int b = blockIdx.x, tid = threadIdx.x;
    __shared__ float red[256];
    float cnt = 0.f;
    #pragma unroll
    for (int p = 0; p < 8; p++) cnt += cntp[b * 8 + p];
    float inv = 1.f / fmaxf(cnt, 1e-9f);
    float pooled[4];
    #pragma unroll
    for (int j = 0; j < 4; j++) {
        int col = tid + j * 256;
        float sum = 0.f;
        #pragma unroll
        for (int p = 0; p < 8; p++) sum += pool[(size_t)(b * 8 + p) * 1024 + col];
        pooled[j] = sum * inv;
    }
    for (int c = 0; c < 2; c++) {
        float pv = 0.f;
        #pragma unroll
        for (int j = 0; j < 4; j++) {
            int k = tid + j * 256;
            pv += pooled[j] * fcW[c * 1024 + k];
        }
        red[tid] = pv;
        __syncthreads();
        for (int st = 128; st > 0; st >>= 1) {
            if (tid < st) red[tid] += red[tid + st];
            __syncthreads();
        }
        if (tid == 0) out[b * 2 + c] = red[0] + fcb[c];
        __syncthreads();
    }
}

// ---------------- host orchestration ----------------
extern "C" void kernel_launch(void* const* d_in, const int* in_sizes, int n_in,
                              void* d_out, int out_size) {
    const int*   x   = (const int*)d_in[0];
    const int*   am  = (const int*)d_in[1];
    const float* emb = (const float*)d_in[2];
    const float* fcW = (const float*)d_in[3];
    const float* fcb = (const float*)d_in[4];
    const float* Wih[2][2] = {{(const float*)d_in[5],  (const float*)d_in[9]},
                              {(const float*)d_in[13], (const float*)d_in[17]}};
    const float* Whh[2][2] = {{(const float*)d_in[6],  (const float*)d_in[10]},
                              {(const float*)d_in[14], (const float*)d_in[18]}};
    const float* bih[2][2] = {{(const float*)d_in[7],  (const float*)d_in[11]},
                              {(const float*)d_in[15], (const float*)d_in[19]}};
    const float* bhh[2][2] = {{(const float*)d_in[8],  (const float*)d_in[12]},
                              {(const float*)d_in[16], (const float*)d_in[20]}};

    void *pX0h, *pX0l, *py0h, *py0l, *py1h, *py1l, *pxp0, *pxp1;
    void *pWihH, *pWihL, *pWhhH, *pWhhL, *pbs, *ppool, *pcnt;
    cudaGetSymbolAddress(&pX0h, g_X0h);
    cudaGetSymbolAddress(&pX0l, g_X0l);
    cudaGetSymbolAddress(&py0h, g_y0h);
    cudaGetSymbolAddress(&py0l, g_y0l);
    cudaGetSymbolAddress(&py1h, g_y1h);
    cudaGetSymbolAddress(&py1l, g_y1l);
    cudaGetSymbolAddress(&pxp0, g_xp0);
    cudaGetSymbolAddress(&pxp1, g_xp1);
    cudaGetSymbolAddress(&pWihH, g_Wih_h);
    cudaGetSymbolAddress(&pWihL, g_Wih_l);
    cudaGetSymbolAddress(&pWhhH, g_Whh_h);
    cudaGetSymbolAddress(&pWhhL, g_Whh_l);
    cudaGetSymbolAddress(&pbs,  g_bsum);
    cudaGetSymbolAddress(&ppool, g_pool);
    cudaGetSymbolAddress(&pcnt,  g_cntp);

    cudaFuncSetAttribute(k_rec,  cudaFuncAttributeMaxDynamicSharedMemorySize, RECSM);
    cudaFuncSetAttribute(k_gemm, cudaFuncAttributeMaxDynamicSharedMemorySize, GSM3);

    const size_t WIH_STRIDE = WIHS;
    const size_t WHH_STRIDE = WHHS;

    // fused prep (1 launch)
    k_prep<<<PR_BLOCKS, 256>>>(x, emb, (__half*)pX0h, (__half*)pX0l,
                               Wih[0][0], Wih[0][1], Wih[1][0], Wih[1][1],
                               Whh[0][0], Whh[0][1], Whh[1][0], Whh[1][1],
                               (__half*)pWihH, (__half*)pWihL,
                               (__half*)pWhhH, (__half*)pWhhL,
                               bih[0][0], bhh[0][0], bih[0][1], bhh[0][1],
                               bih[1][0], bhh[1][0], bih[1][1], bhh[1][1],
                               (float*)pbs);

    dim3 gg(G4H / GBN, BS_ / GBM);   // (16, 128)

    // ----- layer 0 -----
    k_gemm<<<gg, 256, GSM3>>>((const __half*)pX0h, (const __half*)pX0l,
                              (const __half*)pWihH + 0 * WIH_STRIDE,
                              (const __half*)pWihL + 0 * WIH_STRIDE, (float*)pxp0, E_);
    k_gemm<<<gg, 256, GSM3>>>((const __half*)pX0h, (const __half*)pX0l,
                              (const __half*)pWihH + 1 * WIH_STRIDE,
                              (const __half*)pWihL + 1 * WIH_STRIDE, (float*)pxp1, E_);
    k_rec<<<RNB, 128, RECSM>>>((const float*)pxp0, (const float*)pxp1,
                               (const __half*)pWhhH + 0 * WHH_STRIDE,
                               (const __half*)pWhhL + 0 * WHH_STRIDE,
                               (const __half*)pWhhH + 1 * WHH_STRIDE,
                               (const __half*)pWhhL + 1 * WHH_STRIDE,
                               (const float*)pbs + 0 * G4H, (const float*)pbs + 1 * G4H,
                               (__half*)py0h, (__half*)py0l);

    // ----- layer 1 -----
    k_gemm<<<gg, 256, GSM3>>>((const __half*)py0h, (const __half*)py0l,
                              (const __half*)pWihH + 2 * WIH_STRIDE,
                              (const __half*)pWihL + 2 * WIH_STRIDE, (float*)pxp0, 2 * H_);
    k_gemm<<<gg, 256, GSM3>>>((const __half*)py0h, (const __half*)py0l,
                              (const __half*)pWihH + 3 * WIH_STRIDE,
                              (const __half*)pWihL + 3 * WIH_STRIDE, (float*)pxp1, 2 * H_);
    k_rec<<<RNB, 128, RECSM>>>((const float*)pxp0, (const float*)pxp1,
                               (const __half*)pWhhH + 2 * WHH_STRIDE,
                               (const __half*)pWhhL + 2 * WHH_STRIDE,
                               (const __half*)pWhhH + 3 * WHH_STRIDE,
                               (const __half*)pWhhL + 3 * WHH_STRIDE,
                               (const float*)pbs + 2 * G4H, (const float*)pbs + 3 * G4H,
                               (__half*)py1h, (__half*)py1l);

    // ----- pool + fc -----
    k_ppart<<<dim3(32, 8), 256>>>((const __half*)py1h, (const __half*)py1l, am,
                                  (float*)ppool, (float*)pcnt);
    k_fc<<<32, 256>>>((const float*)ppool, (const float*)pcnt, fcW, fcb, (float*)d_out);
}